// round 17
// baseline (speedup 1.0000x reference)
#include <cuda_runtime.h>

#define G_SEG   20000
#define M_MEM   5120000
#define D_FEAT  256

#define MEMBER_BLOCKS 5000            // (M/4)/256
#define GEMV_BLOCKS   2500            // 20000 warps / 8 warps per block
#define TOTAL_BLOCKS  (MEMBER_BLOCKS + GEMV_BLOCKS)

// Per-glimpse accumulators: {sum_e, sum_e*px, sum_e*py, sum_e*pz}.
// 20000 * 16B = 320 KB, L2-resident. Zero-initialized at module load;
// finalize_kernel re-zeroes after reading, so every graph replay starts clean.
// Single table: replica count was measured perf-neutral at R=1,2,4,8 (the
// per-address atomic arrival interval ~75 cyc exceeds L2 atomic service).
__device__ float4 g_acc[G_SEG];

// One vectorized reduction per member: red.global.add.v4.f32 (sm_90+).
__device__ __forceinline__ void red_v4(float4* p, float a, float b, float c, float d) {
    asm volatile("red.global.add.v4.f32 [%0], {%1, %2, %3, %4};"
                 :: "l"(p), "f"(a), "f"(b), "f"(c), "f"(d)
                 : "memory");
}

// Fused kernel, 2:1 interleaved roles (best measured core; member path sits
// at the L1tex scatter-wavefront floor ~40us):
//   blockIdx % 3 != 2 -> member scatter-reduce (4 members/thread)
//   blockIdx % 3 == 2 -> GEMV + presence logits (writes out cols 0-1)
__global__ __launch_bounds__(256, 8) void fused_kernel(
    const float4* __restrict__ pos4,
    const float4* __restrict__ lm4,
    const int4*   __restrict__ idx4,
    const float*  __restrict__ gf,     // (G, 256)
    const float*  __restrict__ Wv,     // (256,)
    const float*  __restrict__ bv,     // (1,)
    const float*  __restrict__ u,      // (G,)
    const float*  __restrict__ temp,   // scalar
    float*        __restrict__ out)    // (G, 5)
{
    const unsigned bidx  = blockIdx.x;
    const unsigned triad = bidx / 3u;
    const unsigned role  = bidx % 3u;

    if (role != 2u) {
        // ---- member scatter-reduce: 4 members per thread ----
        int t = (int)(triad * 2u + role) * blockDim.x + threadIdx.x;  // 0..M/4-1

        // Front-batch all 5 vector loads (idx, lm, 3x pos) for MLP.
        float4 lm = lm4[t];
        int4   ix = idx4[t];
        float4 p0 = pos4[3 * t + 0];
        float4 p1 = pos4[3 * t + 1];
        float4 p2 = pos4[3 * t + 2];

        float e0 = __expf(lm.x);
        float e1 = __expf(lm.y);
        float e2 = __expf(lm.z);
        float e3 = __expf(lm.w);

        red_v4(&g_acc[ix.x], e0, e0 * p0.x, e0 * p0.y, e0 * p0.z);
        red_v4(&g_acc[ix.y], e1, e1 * p0.w, e1 * p1.x, e1 * p1.y);
        red_v4(&g_acc[ix.z], e2, e2 * p1.z, e2 * p1.w, e2 * p2.x);
        red_v4(&g_acc[ix.w], e3, e3 * p2.y, e3 * p2.z, e3 * p2.w);
    } else {
        // ---- warp-per-glimpse GEMV: 8 warps/block ----
        int gw   = (int)triad * 8 + (threadIdx.x >> 5);
        int lane = threadIdx.x & 31;
        if (gw >= G_SEG) return;

        const float4* row = (const float4*)(gf + (size_t)gw * D_FEAT);
        const float4* w4  = (const float4*)Wv;

        float s = 0.f;
#pragma unroll
        for (int k = 0; k < 2; k++) {
            float4 a = row[lane + 32 * k];
            float4 w = w4[lane + 32 * k];
            s += a.x * w.x + a.y * w.y + a.z * w.z + a.w * w.w;
        }
#pragma unroll
        for (int o = 16; o; o >>= 1) s += __shfl_xor_sync(0xFFFFFFFFu, s, o);

        if (lane == 0) {
            float logit = 8.8f * tanhf(s + bv[0]);
            float uu = u[gw];
            float relaxed = (logit + logf(uu) - log1pf(-uu)) / temp[0];
            float lzp = fminf(relaxed, 0.f) - log1pf(__expf(-fabsf(relaxed)));
            float* o5 = out + (size_t)gw * 5;
            o5[0] = lzp;
            o5[1] = logit;
        }
    }
}

// Finalize (fastest measured shape): 256-thread blocks, one glimpse per
// thread, direct loads/stores, no smem. Reads the hot-L2 accumulator,
// re-zeroes it for the next graph replay, writes center cols 2-4.
__global__ __launch_bounds__(256) void finalize_kernel(float* __restrict__ out)
{
    int g = blockIdx.x * blockDim.x + threadIdx.x;
    if (g >= G_SEG) return;

    float4 a = g_acc[g];
    g_acc[g] = make_float4(0.f, 0.f, 0.f, 0.f);

    float inv = 1.f / a.x;
    float* o5 = out + (size_t)g * 5;
    o5[2] = a.y * inv;
    o5[3] = a.z * inv;
    o5[4] = a.w * inv;
}

extern "C" void kernel_launch(void* const* d_in, const int* in_sizes, int n_in,
                              void* d_out, int out_size)
{
    const float* gf   = (const float*)d_in[0];   // glimpse_feature (G, 256)
    const float* pos  = (const float*)d_in[1];   // member_local_pos (M, 3)
    const float* lm   = (const float*)d_in[2];   // member_log_mask (M, 1)
    const int*   idx  = (const int*)  d_in[3];   // member_glimpse_index (M,)
    const float* u    = (const float*)d_in[4];   // u (G,)
    const float* Wv   = (const float*)d_in[5];   // W (256, 1)
    const float* bv   = (const float*)d_in[6];   // b (1,)
    const float* temp = (const float*)d_in[7];   // temperature scalar

    fused_kernel<<<TOTAL_BLOCKS, 256>>>(
        (const float4*)pos, (const float4*)lm, (const int4*)idx,
        gf, Wv, bv, u, temp, (float*)d_out);

    finalize_kernel<<<(G_SEG + 255) / 256, 256>>>((float*)d_out);
}